// round 1
// baseline (speedup 1.0000x reference)
#include <cuda_runtime.h>

#define NB 1024
#define NR 512
#define ND 128
#define NO 64
#define BETA 6.5f
#define LAM_A 0.0033f
#define LAM_W 0.003f

// scratch (allocation-free rule: __device__ globals)
__device__ float g_s[NB * NR];
__device__ float g_h[NB * NR];
__device__ float g_gx[NB * NO];

// ---------------------------------------------------------------------------
// K1: per (b,r): q = sum_d attn*(z-c)^2 ; d=sqrt(q); s=exp(-beta*d);
//     h = -0.5*beta*s/d   (coef for attention grad chain rule)
// 4 batch rows per block to amortize rbf_nodes L2 reads.
// ---------------------------------------------------------------------------
__global__ __launch_bounds__(256) void k1_dist(
    const float* __restrict__ z, const float* __restrict__ attn,
    const float* __restrict__ c)
{
    const int G = 4;
    __shared__ float zs[G][ND];
    __shared__ float as[G][ND];
    int b0 = blockIdx.x * G;
    int tid = threadIdx.x;
    for (int i = tid; i < G * ND; i += 256) {
        int g = i >> 7, d = i & 127;
        zs[g][d] = z[(b0 + g) * ND + d];
        as[g][d] = attn[(b0 + g) * ND + d];
    }
    __syncthreads();

    int warp = tid >> 5, lane = tid & 31;
    for (int r = warp; r < NR; r += 8) {
        const float* cr = c + r * ND;
        float c0 = __ldg(cr + lane);
        float c1 = __ldg(cr + lane + 32);
        float c2 = __ldg(cr + lane + 64);
        float c3 = __ldg(cr + lane + 96);
#pragma unroll
        for (int g = 0; g < G; g++) {
            float d0 = zs[g][lane]      - c0;
            float d1 = zs[g][lane + 32] - c1;
            float d2 = zs[g][lane + 64] - c2;
            float d3 = zs[g][lane + 96] - c3;
            float acc = d0 * d0 * as[g][lane]
                      + d1 * d1 * as[g][lane + 32]
                      + d2 * d2 * as[g][lane + 64]
                      + d3 * d3 * as[g][lane + 96];
#pragma unroll
            for (int off = 16; off; off >>= 1)
                acc += __shfl_xor_sync(0xffffffffu, acc, off);
            if (lane == 0) {
                float dd = sqrtf(acc);
                float s  = __expf(-BETA * dd);
                g_s[(b0 + g) * NR + r] = s;
                g_h[(b0 + g) * NR + r] = -0.5f * BETA * s / dd;
            }
        }
    }
}

// ---------------------------------------------------------------------------
// K2: x_out[b,o] = sum_r s[b,r]*assoc[b,r,o]; teacher; g_x; write 2*x_out
// One block per b; streams 128KB of assoc per block (read once total).
// ---------------------------------------------------------------------------
__global__ __launch_bounds__(256) void k2_forward(
    const float* __restrict__ assoc, const float* __restrict__ label,
    float* __restrict__ out_x)
{
    __shared__ float ss[NR];
    __shared__ float red[4][NO];
    int b = blockIdx.x;
    int tid = threadIdx.x;
    for (int i = tid; i < NR; i += 256) ss[i] = g_s[b * NR + i];
    __syncthreads();

    int o = tid & 63, q = tid >> 6;
    const float* ab = assoc + (size_t)b * NR * NO;
    float acc = 0.f;
#pragma unroll 4
    for (int r = q; r < NR; r += 4)
        acc += ss[r] * __ldg(ab + r * NO + o);
    red[q][o] = acc;
    __syncthreads();

    if (tid < NO) {
        float x = red[0][tid] + red[1][tid] + red[2][tid] + red[3][tid];
        float l = label[b * NO + tid];
        float tmin = fminf(-1.f, x);
        float teacher = tmin - l * tmin + l * fmaxf(1.f, x);
        out_x[b * NO + tid]  = 2.f * x;            // PHI = 2
        g_gx[b * NO + tid] = 0.03125f * (x - teacher);  // 2/O * (x - teacher)
    }
}

// ---------------------------------------------------------------------------
// K3: per b:
//  Phase A: per r: gs = sum_o g_x*assoc ; new_assoc = assoc - lam_w*s*g_x ;
//           coef[r] = h[r]*gs
//  Phase B: grad_attn[k] = sum_r coef[r]*(z[k]-c[r,k])^2 ;
//           new_attn = max(attn - lam_a*grad, 0)
// ---------------------------------------------------------------------------
__global__ __launch_bounds__(256) void k3_backward(
    const float* __restrict__ assoc, const float* __restrict__ z,
    const float* __restrict__ attn, const float* __restrict__ c,
    float* __restrict__ out_attn, float* __restrict__ out_assoc)
{
    __shared__ __align__(8) float gx[NO];
    __shared__ float ss[NR];
    __shared__ float hh[NR];
    __shared__ float coef[NR];
    __shared__ float zsh[ND];
    __shared__ float red[2][ND];

    int b = blockIdx.x;
    int tid = threadIdx.x;
    for (int i = tid; i < NR; i += 256) {
        ss[i] = g_s[b * NR + i];
        hh[i] = g_h[b * NR + i];
    }
    if (tid < NO)  gx[tid]  = g_gx[b * NO + tid];
    if (tid < ND)  zsh[tid] = z[b * ND + tid];
    __syncthreads();

    int warp = tid >> 5, lane = tid & 31;
    const float2* ab = (const float2*)(assoc + (size_t)b * NR * NO);
    float2*       ob = (float2*)(out_assoc + (size_t)b * NR * NO);
    float2 g2 = ((const float2*)gx)[lane];

    for (int r = warp; r < NR; r += 8) {
        float2 a = __ldg(ab + r * 32 + lane);
        float p = a.x * g2.x + a.y * g2.y;
        float f = LAM_W * ss[r];
        float2 ov;
        ov.x = a.x - f * g2.x;
        ov.y = a.y - f * g2.y;
        ob[r * 32 + lane] = ov;
#pragma unroll
        for (int off = 16; off; off >>= 1)
            p += __shfl_xor_sync(0xffffffffu, p, off);
        if (lane == 0) coef[r] = hh[r] * p;
    }
    __syncthreads();

    // Phase B: attention gradient
    int k = tid & 127, half = tid >> 7;
    float zk = zsh[k];
    float acc = 0.f;
#pragma unroll 4
    for (int r = half; r < NR; r += 2) {
        float dd = zk - __ldg(c + r * ND + k);
        acc += coef[r] * dd * dd;
    }
    red[half][k] = acc;
    __syncthreads();

    if (tid < ND) {
        float gsum = red[0][tid] + red[1][tid];
        float na = attn[b * ND + tid] - LAM_A * gsum;
        out_attn[b * ND + tid] = fmaxf(na, 0.f);
    }
}

// ---------------------------------------------------------------------------
extern "C" void kernel_launch(void* const* d_in, const int* in_sizes, int n_in,
                              void* d_out, int out_size)
{
    const float* z     = (const float*)d_in[0];  // (B,D)
    const float* label = (const float*)d_in[1];  // (B,O)
    const float* attn  = (const float*)d_in[2];  // (B,D)
    const float* assoc = (const float*)d_in[3];  // (B,R,O)
    const float* c     = (const float*)d_in[4];  // (R,D)

    float* out       = (float*)d_out;
    float* out_x     = out;                       // (B,O)
    float* out_attn  = out + NB * NO;             // (B,D)
    float* out_assoc = out + NB * NO + NB * ND;   // (B,R,O)

    k1_dist<<<NB / 4, 256>>>(z, attn, c);
    k2_forward<<<NB, 256>>>(assoc, label, out_x);
    k3_backward<<<NB, 256>>>(assoc, z, attn, c, out_attn, out_assoc);
}

// round 2
// speedup vs baseline: 1.9294x; 1.9294x over previous
#include <cuda_runtime.h>

#define NB 1024
#define NR 512
#define ND 128
#define NO 64
#define BETA 6.5f
#define LAM_A 0.0033f
#define LAM_W 0.003f

// scratch (allocation-free rule: __device__ globals)
__device__ float g_s[NB * NR];
__device__ float g_h[NB * NR];
__device__ float g_coef[NB * NR];
__device__ float g_P[NB];
__device__ float g_Q[2 * NB * ND];
__device__ float g_S[2 * NB * ND];

// ---------------------------------------------------------------------------
// K1: distances as GEMM.  q[b,r] = t0[b] + sum_d (-2 a z)[b,d]*c[r,d] + a[b,d]*c^2[r,d]
// 64x64 tile, K=128 d-steps (2 FMA each), 4x4 micro-tile, 256 threads.
// Epilogue: s = exp(-beta*sqrt(q)), h = -0.5*beta*s/sqrt(q).
// ---------------------------------------------------------------------------
#define K1_BM 64
#define K1_BN 64
#define K1_BK 16

__global__ __launch_bounds__(256) void k1_gemm(
    const float* __restrict__ z, const float* __restrict__ attn,
    const float* __restrict__ c)
{
    __shared__ float Au[K1_BK][K1_BM];   // -2*a*z
    __shared__ float Av[K1_BK][K1_BM];   // a
    __shared__ float Bc[K1_BK][K1_BN];   // c
    __shared__ float Bq[K1_BK][K1_BN];   // c^2
    __shared__ float t0s[K1_BM];

    int bm0 = blockIdx.x * K1_BM;   // batch tile
    int bn0 = blockIdx.y * K1_BN;   // rbf tile
    int tid = threadIdx.x;

    // t0[b] = sum_d a*z^2  (4 threads per row, quad shuffle reduce)
    {
        int row = tid >> 2, part = tid & 3;
        const float* zp = z + (bm0 + row) * ND + part * 32;
        const float* ap = attn + (bm0 + row) * ND + part * 32;
        float t = 0.f;
#pragma unroll 8
        for (int d0 = 0; d0 < 32; d0++) { float zz = zp[d0]; t = fmaf(ap[d0] * zz, zz, t); }
        t += __shfl_xor_sync(0xffffffffu, t, 1);
        t += __shfl_xor_sync(0xffffffffu, t, 2);
        if (part == 0) t0s[row] = t;
    }

    float acc[4][4] = {};
    int tm = tid >> 4, tn = tid & 15;

    for (int kc = 0; kc < ND; kc += K1_BK) {
        __syncthreads();
#pragma unroll
        for (int it = 0; it < 4; it++) {
            int i = tid + it * 256;
            int row = i >> 4, dcol = i & 15;
            float a  = attn[(bm0 + row) * ND + kc + dcol];
            float zz = z[(bm0 + row) * ND + kc + dcol];
            Au[dcol][row] = -2.f * a * zz;
            Av[dcol][row] = a;
            float cc = c[(bn0 + row) * ND + kc + dcol];
            Bc[dcol][row] = cc;
            Bq[dcol][row] = cc * cc;
        }
        __syncthreads();
#pragma unroll
        for (int kk = 0; kk < K1_BK; kk++) {
            float4 u = *(const float4*)&Au[kk][tm * 4];
            float4 v = *(const float4*)&Av[kk][tm * 4];
            float4 cc = *(const float4*)&Bc[kk][tn * 4];
            float4 qq = *(const float4*)&Bq[kk][tn * 4];
            float ui[4] = {u.x, u.y, u.z, u.w};
            float vi[4] = {v.x, v.y, v.z, v.w};
            float cj[4] = {cc.x, cc.y, cc.z, cc.w};
            float qj[4] = {qq.x, qq.y, qq.z, qq.w};
#pragma unroll
            for (int i = 0; i < 4; i++)
#pragma unroll
                for (int j = 0; j < 4; j++)
                    acc[i][j] = fmaf(ui[i], cj[j], fmaf(vi[i], qj[j], acc[i][j]));
        }
    }

#pragma unroll
    for (int i = 0; i < 4; i++) {
        int b = bm0 + tm * 4 + i;
        float t0 = t0s[tm * 4 + i];
        float4 so, ho;
        float* sp = &so.x; float* hp = &ho.x;
#pragma unroll
        for (int j = 0; j < 4; j++) {
            float q = fmaxf(acc[i][j] + t0, 1e-12f);
            float dd = sqrtf(q);
            float s = __expf(-BETA * dd);
            sp[j] = s;
            hp[j] = -0.5f * BETA * s / dd;
        }
        *(float4*)&g_s[b * NR + bn0 + tn * 4] = so;
        *(float4*)&g_h[b * NR + bn0 + tn * 4] = ho;
    }
}

// ---------------------------------------------------------------------------
// K23: one block per b.  Phase 1: stream assoc from DRAM, accumulate x inline.
// Compute teacher/gx.  Phase A: re-read assoc (L2-hot), write new_assoc,
// compute coef[r] = h[r]*sum_o gx*assoc, P = sum_r coef.
// ---------------------------------------------------------------------------
__global__ __launch_bounds__(512) void k23(
    const float* __restrict__ assoc, const float* __restrict__ label,
    float* __restrict__ out_x, float* __restrict__ out_assoc)
{
    __shared__ float ss[NR];
    __shared__ float hh[NR];
    __shared__ float red[8][NO];
    __shared__ __align__(16) float gx[NO];
    __shared__ __align__(16) float coef[NR];

    int b = blockIdx.x;
    int tid = threadIdx.x;
    for (int i = tid; i < NR; i += 512) {
        ss[i] = g_s[b * NR + i];
        hh[i] = g_h[b * NR + i];
    }
    __syncthreads();

    const float* ab = assoc + (size_t)b * NR * NO;

    // Phase 1: x[o] = sum_r s[r]*assoc[r,o]
    {
        int o = tid & 63, g = tid >> 6;  // 8 r-groups
        float acc = 0.f;
        const float* p = ab + g * NO + o;
#pragma unroll 8
        for (int i = 0; i < NR / 8; i++)
            acc = fmaf(ss[g + 8 * i], __ldg(p + 8 * i * NO), acc);
        red[g][o] = acc;
    }
    __syncthreads();
    if (tid < NO) {
        float x = 0.f;
#pragma unroll
        for (int g2 = 0; g2 < 8; g2++) x += red[g2][tid];
        float l = label[b * NO + tid];
        float tmin = fminf(-1.f, x);
        float teacher = tmin - l * tmin + l * fmaxf(1.f, x);
        out_x[b * NO + tid] = 2.f * x;                 // PHI = 2
        gx[tid] = 0.03125f * (x - teacher);            // (2/O)*(x - teacher)
    }
    __syncthreads();

    // Phase A: per-r dot with gx (L2-hot re-read), write new_assoc, coef
    int warp = tid >> 5, lane = tid & 31;
    float2 g2v = ((const float2*)gx)[lane];
    const float2* ab2 = (const float2*)ab;
    float2* ob2 = (float2*)(out_assoc + (size_t)b * NR * NO);
    for (int r = warp; r < NR; r += 16) {
        float2 a = __ldg(ab2 + r * 32 + lane);
        float p = fmaf(a.x, g2v.x, a.y * g2v.y);
        float f = LAM_W * ss[r];
        float2 ov = make_float2(fmaf(-f, g2v.x, a.x), fmaf(-f, g2v.y, a.y));
        ob2[r * 32 + lane] = ov;
#pragma unroll
        for (int off = 16; off; off >>= 1)
            p += __shfl_xor_sync(0xffffffffu, p, off);
        if (lane == 0) coef[r] = hh[r] * p;
    }
    __syncthreads();

    if (tid < NR / 4)
        ((float4*)&g_coef[b * NR])[tid] = ((const float4*)coef)[tid];
    if (warp == 0) {
        float p = 0.f;
#pragma unroll
        for (int i = 0; i < 16; i++) p += coef[lane + 32 * i];
#pragma unroll
        for (int off = 16; off; off >>= 1)
            p += __shfl_xor_sync(0xffffffffu, p, off);
        if (lane == 0) g_P[b] = p;
    }
}

// ---------------------------------------------------------------------------
// K4: dual GEMM  Q = coef @ C,  S = coef @ C^2   (M=1024, N=128, K=512)
// split-K=2, 64x32 tiles, 4x2 micro, 256 threads -> 128 blocks.
// ---------------------------------------------------------------------------
#define K4_BM 64
#define K4_BN 32
#define K4_BK 16

__global__ __launch_bounds__(256) void k4_gemm(const float* __restrict__ c)
{
    __shared__ float Ac[K4_BK][K4_BM];
    __shared__ float Bc[K4_BK][K4_BN];
    __shared__ float Bq[K4_BK][K4_BN];

    int bm0 = blockIdx.x * K4_BM;   // b
    int bn0 = blockIdx.y * K4_BN;   // d
    int ks  = blockIdx.z;           // k-split
    int r0  = ks * (NR / 2);
    int tid = threadIdx.x;
    int tm = tid >> 4, tn = tid & 15;

    float aq[4][2] = {};
    float as[4][2] = {};

    for (int kc = 0; kc < NR / 2; kc += K4_BK) {
        __syncthreads();
#pragma unroll
        for (int it = 0; it < 4; it++) {
            int i = tid + it * 256;
            int row = i >> 4, col = i & 15;
            Ac[col][row] = g_coef[(bm0 + row) * NR + r0 + kc + col];
        }
#pragma unroll
        for (int it = 0; it < 2; it++) {
            int i = tid + it * 256;
            int row = i >> 5, col = i & 31;
            float cc = c[(r0 + kc + row) * ND + bn0 + col];
            Bc[row][col] = cc;
            Bq[row][col] = cc * cc;
        }
        __syncthreads();
#pragma unroll
        for (int kk = 0; kk < K4_BK; kk++) {
            float4 a4 = *(const float4*)&Ac[kk][tm * 4];
            float2 c2 = *(const float2*)&Bc[kk][tn * 2];
            float2 q2 = *(const float2*)&Bq[kk][tn * 2];
            float ai[4] = {a4.x, a4.y, a4.z, a4.w};
#pragma unroll
            for (int i = 0; i < 4; i++) {
                aq[i][0] = fmaf(ai[i], c2.x, aq[i][0]);
                aq[i][1] = fmaf(ai[i], c2.y, aq[i][1]);
                as[i][0] = fmaf(ai[i], q2.x, as[i][0]);
                as[i][1] = fmaf(ai[i], q2.y, as[i][1]);
            }
        }
    }
#pragma unroll
    for (int i = 0; i < 4; i++) {
        int b = bm0 + tm * 4 + i;
        int k = bn0 + tn * 2;
        *(float2*)&g_Q[(ks * NB + b) * ND + k] = make_float2(aq[i][0], aq[i][1]);
        *(float2*)&g_S[(ks * NB + b) * ND + k] = make_float2(as[i][0], as[i][1]);
    }
}

// ---------------------------------------------------------------------------
// K5: new_attn = max(attn - lam_a*(z^2*P - 2z*Q + S), 0)
// ---------------------------------------------------------------------------
__global__ __launch_bounds__(256) void k5_attn(
    const float* __restrict__ z, const float* __restrict__ attn,
    float* __restrict__ out_attn)
{
    int idx = blockIdx.x * 256 + threadIdx.x;
    int b = idx >> 7;
    float zz = z[idx];
    float P = g_P[b];
    float Q = g_Q[idx] + g_Q[NB * ND + idx];
    float S = g_S[idx] + g_S[NB * ND + idx];
    float grad = fmaf(zz * zz, P, fmaf(-2.f * zz, Q, S));
    out_attn[idx] = fmaxf(fmaf(-LAM_A, grad, attn[idx]), 0.f);
}

// ---------------------------------------------------------------------------
extern "C" void kernel_launch(void* const* d_in, const int* in_sizes, int n_in,
                              void* d_out, int out_size)
{
    const float* z     = (const float*)d_in[0];  // (B,D)
    const float* label = (const float*)d_in[1];  // (B,O)
    const float* attn  = (const float*)d_in[2];  // (B,D)
    const float* assoc = (const float*)d_in[3];  // (B,R,O)
    const float* c     = (const float*)d_in[4];  // (R,D)

    float* out       = (float*)d_out;
    float* out_x     = out;                       // (B,O)
    float* out_attn  = out + NB * NO;             // (B,D)
    float* out_assoc = out + NB * NO + NB * ND;   // (B,R,O)

    k1_gemm<<<dim3(NB / K1_BM, NR / K1_BN), 256>>>(z, attn, c);
    k23<<<NB, 512>>>(assoc, label, out_x, out_assoc);
    k4_gemm<<<dim3(NB / K4_BM, ND / K4_BN, 2), 256>>>(c);
    k5_attn<<<NB * ND / 256, 256>>>(z, attn, out_attn);
}